// round 4
// baseline (speedup 1.0000x reference)
#include <cuda_runtime.h>

#define BATCH 32
#define HW    16384          // 128*128
#define NPIX  (BATCH * HW)   // 524288
#define NMIXK 10
#define VEC   4
#define TPB   256
#define NBLK  (NPIX / (TPB * VEC))   // 512

__device__ double       g_part[NBLK];
__device__ unsigned int g_count = 0;

// accurate tanh: 2 MUFU (EX2 + RCP), rel err ~1e-6
__device__ __forceinline__ float tanh_acc(float v) {
    float av = fabsf(v);
    float t  = __expf(-2.0f * av);
    float r  = (1.0f - t) * __fdividef(1.0f, 1.0f + t);
    return copysignf(r, v);
}

// per-(channel, mixture) log-prob contribution: 4 MUFU
__device__ __forceinline__ float chlp(float x, float mu, float lsr) {
    float ls   = fmaxf(lsr, -7.0f);
    float inv  = __expf(-ls);
    float cent = x - mu;
    float mid  = inv * cent;
    float d    = inv * (1.0f / 255.0f);       // half-width, > 0
    float am   = fabsf(mid);

    // sinh(d), cosh(d): FMA polynomial for d <= 1 (covers ls > -5.54)
    float sh, ch;
    if (d <= 1.0f) {
        float d2 = d * d;
        sh = d * fmaf(d2, fmaf(d2, fmaf(d2, fmaf(d2, 2.7557319e-6f, 1.9841270e-4f),
                                        8.3333333e-3f), 0.16666667f), 1.0f);
        ch = fmaf(d2, fmaf(d2, fmaf(d2, fmaf(d2, 2.4801587e-5f, 1.3888889e-3f),
                                    4.1666667e-2f), 0.5f), 1.0f);
    } else {
        float ed  = __expf(d);
        float edi = __expf(-d);
        sh = 0.5f * (ed - edi);
        ch = 0.5f * (ed + edi);
    }

    // cdf_delta = 2 g sinh(d) / (1 + 2 g cosh(d) + g^2),  g = exp(-|mid|) <= 1
    float g     = __expf(-am);
    float denom = fmaf(2.0f * ch, g, fmaf(g, g, 1.0f));
    float rden  = __fdividef(1.0f, denom);
    float delta = 2.0f * g * sh * rden;

    // single-LG2 select (fallback: log_pdf_mid - log 127.5 with -2*softplus(-|mid|) ~= log rden)
    float arg, lin;
    if (delta > 1e-5f) { arg = delta; lin = 0.0f; }
    else               { arg = rden;  lin = -ls - am - 4.8481164f; }
    float inner = __logf(arg) + lin;

    // rare edge cases (|x| > 0.999): ~0.05% of pixels
    if (x < -0.999f) {
        float pz = mid + d;
        inner = fminf(pz, 0.0f) - __logf(1.0f + __expf(-fabsf(pz)));
    } else if (x > 0.999f) {
        float q = mid - d;
        inner = -fmaxf(q, 0.0f) - __logf(1.0f + __expf(-fabsf(q)));
    }
    return inner;
}

__device__ __forceinline__ float4 ld4(const float* p) {
    return __ldg(reinterpret_cast<const float4*>(p));
}

__global__ void __launch_bounds__(TPB) pixlp_kernel(
    const float* __restrict__ samples, const float* __restrict__ params,
    float* __restrict__ out)
{
    int tid  = blockIdx.x * TPB + threadIdx.x;
    int pix0 = tid * VEC;                     // 4 consecutive hw pixels, same batch
    int b    = pix0 >> 14;
    int hw   = pix0 & (HW - 1);
    const float* sp = samples + (size_t)b * 3   * HW + hw;
    const float* pp = params  + (size_t)b * 100 * HW + hw;

    // samples -> x in [-1, 1)
    float x0[VEC], x1[VEC], x2[VEC];
    {
        float4 s0 = ld4(sp), s1 = ld4(sp + HW), s2 = ld4(sp + 2 * HW);
        const float* f0 = (const float*)&s0;
        const float* f1 = (const float*)&s1;
        const float* f2 = (const float*)&s2;
        #pragma unroll
        for (int p = 0; p < VEC; p++) {
            x0[p] = fmaf(2.0f, f0[p], -1.0f);
            x1[p] = fmaf(2.0f, f1[p], -1.0f);
            x2[p] = fmaf(2.0f, f2[p], -1.0f);
        }
    }

    // online logsumexp states: logits and mixture log-probs
    float mxl[VEC], sl[VEC], mxp[VEC], s2s[VEC];
    #pragma unroll
    for (int p = 0; p < VEC; p++) {
        mxl[p] = -1e30f; sl[p] = 0.0f;
        mxp[p] = -1e30f; s2s[p] = 0.0f;
    }

    #pragma unroll
    for (int m = 0; m < NMIXK; m++) {
        float4 lgv  = ld4(pp + (     m) * HW);
        float4 mu1v = ld4(pp + (10 + m) * HW);
        float4 ls1v = ld4(pp + (20 + m) * HW);
        float4 c0v  = ld4(pp + (30 + m) * HW);
        float4 mu2v = ld4(pp + (40 + m) * HW);
        float4 ls2v = ld4(pp + (50 + m) * HW);
        float4 c1v  = ld4(pp + (60 + m) * HW);
        float4 mu3v = ld4(pp + (70 + m) * HW);
        float4 ls3v = ld4(pp + (80 + m) * HW);
        float4 c2v  = ld4(pp + (90 + m) * HW);

        const float* lg  = (const float*)&lgv;
        const float* mu1 = (const float*)&mu1v;
        const float* ls1 = (const float*)&ls1v;
        const float* c0r = (const float*)&c0v;
        const float* mu2 = (const float*)&mu2v;
        const float* ls2 = (const float*)&ls2v;
        const float* c1r = (const float*)&c1v;
        const float* mu3 = (const float*)&mu3v;
        const float* ls3 = (const float*)&ls3v;
        const float* c2r = (const float*)&c2v;

        #pragma unroll
        for (int p = 0; p < VEC; p++) {
            // online LSE over logits
            float nl = fmaxf(mxl[p], lg[p]);
            sl[p] = fmaf(sl[p], __expf(mxl[p] - nl), __expf(lg[p] - nl));
            mxl[p] = nl;

            float c0 = tanh_acc(c0r[p]);
            float c1 = tanh_acc(c1r[p]);
            float c2 = tanh_acc(c2r[p]);

            float m2 = fmaf(c0, x0[p], mu2[p]);
            float m3 = fmaf(c2, x1[p], fmaf(c1, x0[p], mu3[p]));

            float lpm = lg[p] + chlp(x0[p], mu1[p], ls1[p])
                              + chlp(x1[p], m2,     ls2[p])
                              + chlp(x2[p], m3,     ls3[p]);

            // online LSE over mixtures
            float np = fmaxf(mxp[p], lpm);
            s2s[p] = fmaf(s2s[p], __expf(mxp[p] - np), __expf(lpm - np));
            mxp[p] = np;
        }
    }

    float val = 0.0f;
    #pragma unroll
    for (int p = 0; p < VEC; p++)
        val += (mxp[p] + __logf(s2s[p])) - (mxl[p] + __logf(sl[p]));

    // block reduction (fp32 in block)
    __shared__ float red[TPB];
    int t = threadIdx.x;
    red[t] = val;
    __syncthreads();
    #pragma unroll
    for (int off = TPB / 2; off > 0; off >>= 1) {
        if (t < off) red[t] += red[t + off];
        __syncthreads();
    }

    // block partial -> double; last block finishes (no helper kernels)
    __shared__ bool amLast;
    if (t == 0) {
        g_part[blockIdx.x] = (double)red[0];
        __threadfence();
        unsigned int done = atomicAdd(&g_count, 1u);
        amLast = (done == NBLK - 1);
    }
    __syncthreads();

    if (amLast) {
        __shared__ double redd[TPB];
        double s = 0.0;
        for (int i = t; i < NBLK; i += TPB) s += g_part[i];
        redd[t] = s;
        __syncthreads();
        #pragma unroll
        for (int off = TPB / 2; off > 0; off >>= 1) {
            if (t < off) redd[t] += redd[t + off];
            __syncthreads();
        }
        if (t == 0) {
            out[0] = (float)redd[0];
            g_count = 0;                      // reset for next graph replay
        }
    }
}

extern "C" void kernel_launch(void* const* d_in, const int* in_sizes, int n_in,
                              void* d_out, int out_size)
{
    const float* samples;
    const float* params;
    if (in_sizes[0] == BATCH * 3 * HW) {
        samples = (const float*)d_in[0];
        params  = (const float*)d_in[1];
    } else {
        samples = (const float*)d_in[1];
        params  = (const float*)d_in[0];
    }
    pixlp_kernel<<<NBLK, TPB>>>(samples, params, (float*)d_out);
}

// round 6
// speedup vs baseline: 3.7151x; 3.7151x over previous
#include <cuda_runtime.h>

#define BATCH 32
#define HW    16384          // 128*128
#define NPIX  (BATCH * HW)   // 524288
#define NMIXK 10
#define TPB   256
#define NBLK  (NPIX / TPB)   // 2048

__device__ double       g_part[NBLK];
__device__ unsigned int g_count = 0;

// hardware tanh: 1 MUFU op, abs err ~5e-4 (plenty for 1e-3 final tolerance)
__device__ __forceinline__ float tanh_hw(float v) {
    float r;
    asm("tanh.approx.f32 %0, %1;" : "=f"(r) : "f"(v));
    return r;
}

// per-(channel, mixture) log-prob contribution: 4 MUFU
__device__ __forceinline__ float chlp(float x, float mu, float lsr) {
    float ls   = fmaxf(lsr, -7.0f);
    float inv  = __expf(-ls);                 // MUFU 1
    float cent = x - mu;
    float mid  = inv * cent;
    float d    = inv * (1.0f / 255.0f);       // half-width, > 0
    float am   = fabsf(mid);

    // sinh(d), cosh(d): FMA polynomial for d <= 1 (covers ls > -5.54)
    float sh, ch;
    if (d <= 1.0f) {
        float d2 = d * d;
        sh = d * fmaf(d2, fmaf(d2, fmaf(d2, fmaf(d2, 2.7557319e-6f, 1.9841270e-4f),
                                        8.3333333e-3f), 0.16666667f), 1.0f);
        ch = fmaf(d2, fmaf(d2, fmaf(d2, fmaf(d2, 2.4801587e-5f, 1.3888889e-3f),
                                    4.1666667e-2f), 0.5f), 1.0f);
    } else {
        float ed  = __expf(d);
        float edi = __expf(-d);
        sh = 0.5f * (ed - edi);
        ch = 0.5f * (ed + edi);
    }

    // cdf_delta = sigmoid(mid+d) - sigmoid(mid-d), symmetric, cancellation-free:
    //   delta = 2 g sinh(d) / (1 + 2 g cosh(d) + g^2),  g = exp(-|mid|) <= 1
    float g     = __expf(-am);                           // MUFU 2
    float denom = fmaf(2.0f * ch, g, fmaf(g, g, 1.0f));
    float rden  = __fdividef(1.0f, denom);               // MUFU 3
    float delta = 2.0f * g * sh * rden;

    // single-LG2 select (fallback: log_pdf_mid - log 127.5, using
    //  -2*softplus(-|mid|) ~= log(rden), error <= 1e-5*tanh(d/2))
    float arg, lin;
    if (delta > 1e-5f) { arg = delta; lin = 0.0f; }
    else               { arg = rden;  lin = -ls - am - 4.8481164f; }
    float inner = __logf(arg) + lin;                     // MUFU 4

    // rare edge cases (|x| > 0.999): ~0.05% of pixels
    if (x < -0.999f) {
        float pz = mid + d;
        inner = fminf(pz, 0.0f) - __logf(1.0f + __expf(-fabsf(pz)));
    } else if (x > 0.999f) {
        float q = mid - d;
        inner = -fmaxf(q, 0.0f) - __logf(1.0f + __expf(-fabsf(q)));
    }
    return inner;
}

__global__ void __launch_bounds__(TPB) pixlp_kernel(
    const float* __restrict__ samples, const float* __restrict__ params,
    float* __restrict__ out)
{
    int p  = blockIdx.x * TPB + threadIdx.x;
    int b  = p >> 14;
    int hw = p & (HW - 1);
    const float* sp = samples + (size_t)b * 3   * HW + hw;
    const float* pp = params  + (size_t)b * 100 * HW + hw;

    float x0 = fmaf(2.0f, __ldg(sp),          -1.0f);
    float x1 = fmaf(2.0f, __ldg(sp + HW),     -1.0f);
    float x2 = fmaf(2.0f, __ldg(sp + 2 * HW), -1.0f);

    float se = 0.0f;        // sum exp(logits) — |logits| small, no max needed
    float lp[NMIXK];

    #pragma unroll
    for (int m = 0; m < NMIXK; m++) {
        float lg  = __ldg(pp + (     m) * HW);
        float mu1 = __ldg(pp + (10 + m) * HW);
        float ls1 = __ldg(pp + (20 + m) * HW);
        float c0r = __ldg(pp + (30 + m) * HW);
        float mu2 = __ldg(pp + (40 + m) * HW);
        float ls2 = __ldg(pp + (50 + m) * HW);
        float c1r = __ldg(pp + (60 + m) * HW);
        float mu3 = __ldg(pp + (70 + m) * HW);
        float ls3 = __ldg(pp + (80 + m) * HW);
        float c2r = __ldg(pp + (90 + m) * HW);

        se += __expf(lg);

        float c0 = tanh_hw(c0r);
        float c1 = tanh_hw(c1r);
        float c2 = tanh_hw(c2r);

        float m2 = fmaf(c0, x0, mu2);
        float m3 = fmaf(c2, x1, fmaf(c1, x0, mu3));

        lp[m] = lg + chlp(x0, mu1, ls1)
                   + chlp(x1, m2,  ls2)
                   + chlp(x2, m3,  ls3);
    }

    float mx2 = lp[0];
    #pragma unroll
    for (int i = 1; i < NMIXK; i++) mx2 = fmaxf(mx2, lp[i]);
    float s2 = 0.0f;
    #pragma unroll
    for (int i = 0; i < NMIXK; i++) s2 += __expf(lp[i] - mx2);

    float val = mx2 + __logf(s2) - __logf(se);

    // block reduction (fp32 within block)
    __shared__ float red[TPB];
    int t = threadIdx.x;
    red[t] = val;
    __syncthreads();
    #pragma unroll
    for (int off = TPB / 2; off > 32; off >>= 1) {
        if (t < off) red[t] += red[t + off];
        __syncthreads();
    }
    if (t < 32) {
        float w = red[t] + red[t + 32];
        #pragma unroll
        for (int off = 16; off > 0; off >>= 1)
            w += __shfl_down_sync(0xFFFFFFFFu, w, off);
        if (t == 0) red[0] = w;
    }
    __syncthreads();

    // block partial (double), last block finishes — no helper kernels
    __shared__ bool amLast;
    if (t == 0) {
        g_part[blockIdx.x] = (double)red[0];
        __threadfence();
        unsigned int done = atomicAdd(&g_count, 1u);
        amLast = (done == NBLK - 1);
    }
    __syncthreads();

    if (amLast) {
        __shared__ double redd[TPB];
        double s = 0.0;
        for (int i = t; i < NBLK; i += TPB) s += g_part[i];
        redd[t] = s;
        __syncthreads();
        #pragma unroll
        for (int off = TPB / 2; off > 0; off >>= 1) {
            if (t < off) redd[t] += redd[t + off];
            __syncthreads();
        }
        if (t == 0) {
            out[0] = (float)redd[0];
            g_count = 0;                      // reset for next graph replay
        }
    }
}

extern "C" void kernel_launch(void* const* d_in, const int* in_sizes, int n_in,
                              void* d_out, int out_size)
{
    const float* samples;
    const float* params;
    if (in_sizes[0] == BATCH * 3 * HW) {
        samples = (const float*)d_in[0];
        params  = (const float*)d_in[1];
    } else {
        samples = (const float*)d_in[1];
        params  = (const float*)d_in[0];
    }
    pixlp_kernel<<<NBLK, TPB>>>(samples, params, (float*)d_out);
}

// round 7
// speedup vs baseline: 3.7654x; 1.0135x over previous
#include <cuda_runtime.h>

#define BATCH 32
#define HW    16384          // 128*128
#define NPIX  (BATCH * HW)   // 524288
#define NMIXK 10
#define TPB   256
#define NBLK  (NPIX / TPB)   // 2048

__device__ double       g_part[NBLK];
__device__ unsigned int g_count = 0;

// hardware tanh: 1 MUFU op, abs err ~5e-4
__device__ __forceinline__ float tanh_hw(float v) {
    float r;
    asm("tanh.approx.f32 %0, %1;" : "=f"(r) : "f"(v));
    return r;
}

// per-(channel, mixture) log-prob contribution: 3 MUFU (EX2, EX2, LG2)
//
// cdf_delta = sigmoid(mid+d) - sigmoid(mid-d) = 2 g sinh(d) / denom,
//   g = exp(-|mid|), denom = 1 + 2 g cosh(d) + g^2  (cancellation-free).
// log(cdf_delta) = log(2d) + log(sinh(d)/d) - |mid| - log(denom)
//   with log(2d) = log(2/255) - ls = -4.8481164 - ls   (exact, no MUFU).
// The reference's small-delta fallback (log_pdf_mid - log 127.5) equals the
// SAME expression minus the log(sinh(d)/d) correction (using
// -2*softplus(-|mid|) ~= -log(denom), error <= g*d^2) — so the branch is just
// a predicated add of a 2-FMA polynomial. No RCP anywhere.
__device__ __forceinline__ float chlp(float x, float mu, float lsr) {
    float ls  = fmaxf(lsr, -7.0f);
    float inv = __expf(-ls);                             // MUFU 1
    float mid = inv * (x - mu);
    float d   = inv * (1.0f / 255.0f);                   // half-width > 0
    float am  = fabsf(mid);
    float g   = __expf(-am);                             // MUFU 2

    float d2 = d * d;
    // valid for d <= 1 (ls > -5.54; typical d ~ 4e-3)
    float sh     = d * fmaf(d2, fmaf(d2, 8.3333333e-3f, 0.16666667f), 1.0f);
    float ch     = fmaf(d2, fmaf(d2, 4.1666667e-2f, 0.5f), 1.0f);
    float log_sc = d2 * fmaf(d2, -5.5555556e-3f, 0.16666667f);  // log(sinh d / d)
    float denom  = fmaf(2.0f * ch, g, fmaf(g, g, 1.0f));

    if (d > 1.0f) {                                      // ultra-rare exact path
        float ed = __expf(d), edi = __expf(-d);
        sh     = 0.5f * (ed - edi);
        ch     = 0.5f * (ed + edi);
        denom  = fmaf(2.0f * ch, g, fmaf(g, g, 1.0f));
        log_sc = __logf(sh * __fdividef(1.0f, d));
    }

    // include correction iff cdf_delta = 2 g sh / denom > 1e-5
    float corr  = (2.0f * g * sh > 1e-5f * denom) ? log_sc : 0.0f;
    float inner = -ls - 4.8481164f - am - __logf(denom) + corr;  // MUFU 3

    // rare edge cases (|x| > 0.999): ~0.05% of pixels
    if (x < -0.999f) {
        float pz = mid + d;
        inner = fminf(pz, 0.0f) - __logf(1.0f + __expf(-fabsf(pz)));
    } else if (x > 0.999f) {
        float q = mid - d;
        inner = -fmaxf(q, 0.0f) - __logf(1.0f + __expf(-fabsf(q)));
    }
    return inner;
}

__global__ void __launch_bounds__(TPB) pixlp_kernel(
    const float* __restrict__ samples, const float* __restrict__ params,
    float* __restrict__ out)
{
    int p  = blockIdx.x * TPB + threadIdx.x;
    int b  = p >> 14;
    int hw = p & (HW - 1);
    const float* sp = samples + (size_t)b * 3   * HW + hw;
    const float* pp = params  + (size_t)b * 100 * HW + hw;

    float x0 = fmaf(2.0f, __ldg(sp),          -1.0f);
    float x1 = fmaf(2.0f, __ldg(sp + HW),     -1.0f);
    float x2 = fmaf(2.0f, __ldg(sp + 2 * HW), -1.0f);

    float se = 0.0f;        // sum exp(logits) — |logits| small, overflow-safe
    float lp[NMIXK];

    #pragma unroll
    for (int m = 0; m < NMIXK; m++) {
        float lg  = __ldg(pp + (     m) * HW);
        float mu1 = __ldg(pp + (10 + m) * HW);
        float ls1 = __ldg(pp + (20 + m) * HW);
        float c0r = __ldg(pp + (30 + m) * HW);
        float mu2 = __ldg(pp + (40 + m) * HW);
        float ls2 = __ldg(pp + (50 + m) * HW);
        float c1r = __ldg(pp + (60 + m) * HW);
        float mu3 = __ldg(pp + (70 + m) * HW);
        float ls3 = __ldg(pp + (80 + m) * HW);
        float c2r = __ldg(pp + (90 + m) * HW);

        se += __expf(lg);

        float c0 = tanh_hw(c0r);
        float c1 = tanh_hw(c1r);
        float c2 = tanh_hw(c2r);

        float m2 = fmaf(c0, x0, mu2);
        float m3 = fmaf(c2, x1, fmaf(c1, x0, mu3));

        lp[m] = lg + chlp(x0, mu1, ls1)
                   + chlp(x1, m2,  ls2)
                   + chlp(x2, m3,  ls3);
    }

    float mx2 = lp[0];
    #pragma unroll
    for (int i = 1; i < NMIXK; i++) mx2 = fmaxf(mx2, lp[i]);
    float s2 = 0.0f;
    #pragma unroll
    for (int i = 0; i < NMIXK; i++) s2 += __expf(lp[i] - mx2);

    float val = mx2 + __logf(s2) - __logf(se);

    // block reduction (fp32 within block)
    __shared__ float red[TPB];
    int t = threadIdx.x;
    red[t] = val;
    __syncthreads();
    #pragma unroll
    for (int off = TPB / 2; off > 32; off >>= 1) {
        if (t < off) red[t] += red[t + off];
        __syncthreads();
    }
    if (t < 32) {
        float w = red[t] + red[t + 32];
        #pragma unroll
        for (int off = 16; off > 0; off >>= 1)
            w += __shfl_down_sync(0xFFFFFFFFu, w, off);
        if (t == 0) red[0] = w;
    }
    __syncthreads();

    // block partial (double), last block finishes — no helper kernels
    __shared__ bool amLast;
    if (t == 0) {
        g_part[blockIdx.x] = (double)red[0];
        __threadfence();
        unsigned int done = atomicAdd(&g_count, 1u);
        amLast = (done == NBLK - 1);
    }
    __syncthreads();

    if (amLast) {
        __shared__ double redd[TPB];
        double s = 0.0;
        for (int i = t; i < NBLK; i += TPB) s += g_part[i];
        redd[t] = s;
        __syncthreads();
        #pragma unroll
        for (int off = TPB / 2; off > 0; off >>= 1) {
            if (t < off) redd[t] += redd[t + off];
            __syncthreads();
        }
        if (t == 0) {
            out[0] = (float)redd[0];
            g_count = 0;                      // reset for next graph replay
        }
    }
}

extern "C" void kernel_launch(void* const* d_in, const int* in_sizes, int n_in,
                              void* d_out, int out_size)
{
    const float* samples;
    const float* params;
    if (in_sizes[0] == BATCH * 3 * HW) {
        samples = (const float*)d_in[0];
        params  = (const float*)d_in[1];
    } else {
        samples = (const float*)d_in[1];
        params  = (const float*)d_in[0];
    }
    pixlp_kernel<<<NBLK, TPB>>>(samples, params, (float*)d_out);
}

// round 8
// speedup vs baseline: 4.1123x; 1.0921x over previous
#include <cuda_runtime.h>

#define BATCH 32
#define HW    16384          // 128*128
#define NPIX  (BATCH * HW)   // 524288
#define NMIXK 10
#define TPB   256
#define NBLK  (NPIX / TPB)   // 2048

__device__ double       g_part[NBLK];
__device__ unsigned int g_count = 0;

// hardware tanh: 1 MUFU op, abs err ~5e-4
__device__ __forceinline__ float tanh_hw(float v) {
    float r;
    asm("tanh.approx.f32 %0, %1;" : "=f"(r) : "f"(v));
    return r;
}

// per-(channel, mixture) log-prob contribution: 3 MUFU (EX2, EX2, LG2)
//
// cdf_delta = sigmoid(mid+d) - sigmoid(mid-d) = 2 g sinh(d) / denom,
//   g = exp(-|mid|), denom = 1 + 2 g cosh(d) + g^2  (cancellation-free).
// log(cdf_delta) = log(2d) + log(sinh(d)/d) - |mid| - log(denom)
//   with log(2d) = log(2/255) - ls = -4.8481164 - ls   (exact, no MUFU).
// The reference's small-delta fallback (log_pdf_mid - log 127.5) equals the
// SAME expression minus the log(sinh(d)/d) correction (using
// -2*softplus(-|mid|) ~= -log(denom), error <= g*d^2) — so the branch is a
// predicated add of a 2-FMA polynomial. No RCP anywhere.
__device__ __forceinline__ float chlp(float x, float mu, float lsr) {
    float ls  = fmaxf(lsr, -7.0f);
    float inv = __expf(-ls);                             // MUFU 1
    float mid = inv * (x - mu);
    float d   = inv * (1.0f / 255.0f);                   // half-width > 0
    float am  = fabsf(mid);
    float g   = __expf(-am);                             // MUFU 2

    float d2 = d * d;
    // valid for d <= 1 (ls > -5.54; typical d ~ 4e-3)
    float sh     = d * fmaf(d2, fmaf(d2, 8.3333333e-3f, 0.16666667f), 1.0f);
    float ch     = fmaf(d2, fmaf(d2, 4.1666667e-2f, 0.5f), 1.0f);
    float log_sc = d2 * fmaf(d2, -5.5555556e-3f, 0.16666667f);  // log(sinh d / d)
    float denom  = fmaf(2.0f * ch, g, fmaf(g, g, 1.0f));

    if (d > 1.0f) {                                      // ultra-rare exact path
        float ed = __expf(d), edi = __expf(-d);
        sh     = 0.5f * (ed - edi);
        ch     = 0.5f * (ed + edi);
        denom  = fmaf(2.0f * ch, g, fmaf(g, g, 1.0f));
        log_sc = __logf(sh * __fdividef(1.0f, d));
    }

    // include correction iff cdf_delta = 2 g sh / denom > 1e-5
    float corr  = (2.0f * g * sh > 1e-5f * denom) ? log_sc : 0.0f;
    float inner = -ls - 4.8481164f - am - __logf(denom) + corr;  // MUFU 3

    // rare edge cases (|x| > 0.999): ~0.05% of pixels
    if (x < -0.999f) {
        float pz = mid + d;
        inner = fminf(pz, 0.0f) - __logf(1.0f + __expf(-fabsf(pz)));
    } else if (x > 0.999f) {
        float q = mid - d;
        inner = -fmaxf(q, 0.0f) - __logf(1.0f + __expf(-fabsf(q)));
    }
    return inner;
}

__global__ void __launch_bounds__(TPB, 8) pixlp_kernel(
    const float* __restrict__ samples, const float* __restrict__ params,
    float* __restrict__ out)
{
    int p  = blockIdx.x * TPB + threadIdx.x;
    int b  = p >> 14;
    int hw = p & (HW - 1);
    const float* sp = samples + (size_t)b * 3   * HW + hw;
    const float* pp = params  + (size_t)b * 100 * HW + hw;

    float x0 = fmaf(2.0f, __ldg(sp),          -1.0f);
    float x1 = fmaf(2.0f, __ldg(sp + HW),     -1.0f);
    float x2 = fmaf(2.0f, __ldg(sp + 2 * HW), -1.0f);

    float se = 0.0f;        // sum exp(logits) — |logits| small, overflow-safe
    float lp[NMIXK];

    #pragma unroll
    for (int m = 0; m < NMIXK; m++) {
        float lg  = __ldg(pp + (     m) * HW);
        float mu1 = __ldg(pp + (10 + m) * HW);
        float ls1 = __ldg(pp + (20 + m) * HW);
        float c0r = __ldg(pp + (30 + m) * HW);
        float mu2 = __ldg(pp + (40 + m) * HW);
        float ls2 = __ldg(pp + (50 + m) * HW);
        float c1r = __ldg(pp + (60 + m) * HW);
        float mu3 = __ldg(pp + (70 + m) * HW);
        float ls3 = __ldg(pp + (80 + m) * HW);
        float c2r = __ldg(pp + (90 + m) * HW);

        se += __expf(lg);

        float c0 = tanh_hw(c0r);
        float c1 = tanh_hw(c1r);
        float c2 = tanh_hw(c2r);

        float m2 = fmaf(c0, x0, mu2);
        float m3 = fmaf(c2, x1, fmaf(c1, x0, mu3));

        lp[m] = lg + chlp(x0, mu1, ls1)
                   + chlp(x1, m2,  ls2)
                   + chlp(x2, m3,  ls3);
    }

    float mx2 = lp[0];
    #pragma unroll
    for (int i = 1; i < NMIXK; i++) mx2 = fmaxf(mx2, lp[i]);
    float s2 = 0.0f;
    #pragma unroll
    for (int i = 0; i < NMIXK; i++) s2 += __expf(lp[i] - mx2);

    float val = mx2 + __logf(s2) - __logf(se);

    // block reduction (fp32 within block)
    __shared__ float red[TPB];
    int t = threadIdx.x;
    red[t] = val;
    __syncthreads();
    #pragma unroll
    for (int off = TPB / 2; off > 32; off >>= 1) {
        if (t < off) red[t] += red[t + off];
        __syncthreads();
    }
    if (t < 32) {
        float w = red[t] + red[t + 32];
        #pragma unroll
        for (int off = 16; off > 0; off >>= 1)
            w += __shfl_down_sync(0xFFFFFFFFu, w, off);
        if (t == 0) red[0] = w;
    }
    __syncthreads();

    // block partial (double), last block finishes — no helper kernels
    __shared__ bool amLast;
    if (t == 0) {
        g_part[blockIdx.x] = (double)red[0];
        __threadfence();
        unsigned int done = atomicAdd(&g_count, 1u);
        amLast = (done == NBLK - 1);
    }
    __syncthreads();

    if (amLast) {
        __shared__ double redd[TPB];
        double s = 0.0;
        for (int i = t; i < NBLK; i += TPB) s += g_part[i];
        redd[t] = s;
        __syncthreads();
        #pragma unroll
        for (int off = TPB / 2; off > 0; off >>= 1) {
            if (t < off) redd[t] += redd[t + off];
            __syncthreads();
        }
        if (t == 0) {
            out[0] = (float)redd[0];
            g_count = 0;                      // reset for next graph replay
        }
    }
}

extern "C" void kernel_launch(void* const* d_in, const int* in_sizes, int n_in,
                              void* d_out, int out_size)
{
    const float* samples;
    const float* params;
    if (in_sizes[0] == BATCH * 3 * HW) {
        samples = (const float*)d_in[0];
        params  = (const float*)d_in[1];
    } else {
        samples = (const float*)d_in[1];
        params  = (const float*)d_in[0];
    }
    pixlp_kernel<<<NBLK, TPB>>>(samples, params, (float*)d_out);
}